// round 7
// baseline (speedup 1.0000x reference)
#include <cuda_runtime.h>

__device__ unsigned int g_maxabs_u;   // bits of max(|coords|); idempotent across replays

// ---------------------------------------------------------------------------
// K1: max|coords| over float4s (one per thread), warp-reduce + atomicMax.
__global__ void fm_reduce_kernel(const float4* __restrict__ coords4, int n4c) {
    const int i = blockIdx.x * blockDim.x + threadIdx.x;
    float m = 0.0f;
    if (i < n4c) {
        float4 v = coords4[i];
        m = fmaxf(fmaxf(fabsf(v.x), fabsf(v.y)), fmaxf(fabsf(v.z), fabsf(v.w)));
    }
#pragma unroll
    for (int o = 16; o; o >>= 1)
        m = fmaxf(m, __shfl_xor_sync(0xFFFFFFFFu, m, o));
    if ((threadIdx.x & 31) == 0)
        atomicMax(&g_maxabs_u, __float_as_uint(m));
}

// ---------------------------------------------------------------------------
// K2: one WARP per real atom (sentinels provably never reach the crop window).
// Lanes cover the clipped (y,z) footprint with z fastest (coalesced atomics);
// each lane walks x serially using a per-warp exp/exponent table in smem.
__global__ void __launch_bounds__(256)
fm_scatter_kernel(const float* __restrict__ coords,
                  const int*   __restrict__ channel,
                  const float* __restrict__ radius,
                  int L, int BL,
                  float* __restrict__ acc) {
    __shared__ float s_ex[8 * 12];
    __shared__ float s_vx[8 * 12];

    const int wg   = (blockIdx.x * blockDim.x + threadIdx.x) >> 5;
    const int warp = (threadIdx.x >> 5);
    const int lane = threadIdx.x & 31;
    if (wg >= BL) return;
    const int b = wg / L;

    // Scalars from the global max (res = 0.5 -> x/res == x*2 exactly).
    const float maxabs = __uint_as_float(g_maxabs_u);
    const float dumb   = maxabs + 10.0f;
    const float mmin   = truncf(-dumb * 2.0f);       // trunc(min/res)
    const float transl = mmin - 5.0f;                // mincoords - CUBES_AROUND
    const int   box    = (int)(ceilf(dumb * 2.0f) - mmin) + 11;
    const int   lo     = (box + 1) / 2 - 16;         // crop start (global voxel idx)
    const int   hi     = lo + 31;

    const float* p = coords + (size_t)wg * 3;
    const float px = p[0], py = p[1], pz = p[2];
    const int   ch = channel[wg];
    const float rad = radius[wg] * 1.41421356237309515f;   // RADIUS_SCALE

    const float rt    = rad * 2.0f;                  // radius / res
    const float denom = 0.8649f * rt * rt;           // 0.93^2 * rt^2
    const float inv   = 1.0f / denom;
    const float rcut  = sqrtf(10.0f * denom) + 2e-3f;

    const float tx = px * 2.0f - transl;
    const float ty = py * 2.0f - transl;
    const float tz = pz * 2.0f - transl;
    const int   dx = (int)truncf(tx);
    const int   dy = (int)truncf(ty);
    const int   dz = (int)truncf(tz);

    // Per-dim clipped global-voxel ranges: cube ∩ cutoff-box ∩ crop.
    const int x0 = max(max(dx - 4, lo), (int)ceilf (tx - 0.25f - rcut));
    const int x1 = min(min(dx + 6, hi), (int)floorf(tx - 0.25f + rcut));
    const int y0 = max(max(dy - 4, lo), (int)ceilf (ty - 0.25f - rcut));
    const int y1 = min(min(dy + 6, hi), (int)floorf(ty - 0.25f + rcut));
    const int z0 = max(max(dz - 4, lo), (int)ceilf (tz - 0.25f - rcut));
    const int z1 = min(min(dz + 6, hi), (int)floorf(tz - 0.25f + rcut));

    const int nx = x1 - x0 + 1, ny = y1 - y0 + 1, nz = z1 - z0 + 1;
    if (nx <= 0 || ny <= 0 || nz <= 0) return;

    // Per-warp x tables (filters above are warp-uniform).
    float* exw = s_ex + warp * 12;
    float* vxw = s_vx + warp * 12;
    if (lane < nx) {
        const float dd = tx - ((float)(x0 + lane) + 0.25f);
        const float ex = dd * dd * inv;
        exw[lane] = ex;
        vxw[lane] = __expf(-ex);
    }
    __syncwarp();

    // Base global index for x0: layout [B, C, X, Y, Z].
    const int base = (((b * 5 + ch) * 32 + (x0 - lo)) << 10);
    const int total_yz = ny * nz;

    for (int t = lane; t < total_yz; t += 32) {
        const int izr = t % nz;
        const int iyr = t / nz;
        const int gyi = y0 + iyr, gzi = z0 + izr;

        const float ddy = ty - ((float)gyi + 0.25f);
        const float ddz = tz - ((float)gzi + 0.25f);
        const float eyz = (ddy * ddy + ddz * ddz) * inv;
        if (eyz >= 10.0f) continue;                  // whole x-run masked
        const float vyz = __expf(-eyz);

        int idx = base + ((gyi - lo) << 5) + (gzi - lo);
#pragma unroll 4
        for (int xi = 0; xi < nx; ++xi, idx += 1024) {
            const float e = exw[xi] + eyz;
            if (e < 10.0f) {
                const float val = __logf(1.0f - vxw[xi] * vyz);
                atomicAdd(acc + idx, val);
            }
        }
    }
}

// ---------------------------------------------------------------------------
// K3: in-place out = 1 - exp(out); all-zero float4 fast path; 2 quads/thread.
__global__ void fm_finalize_kernel(float4* __restrict__ out, int n4) {
    const int i0 = (blockIdx.x * blockDim.x + threadIdx.x) * 2;
#pragma unroll
    for (int k = 0; k < 2; ++k) {
        const int i = i0 + k;
        if (i >= n4) return;
        float4 v = out[i];
        if ((__float_as_uint(v.x) | __float_as_uint(v.y) |
             __float_as_uint(v.z) | __float_as_uint(v.w)) == 0u)
            continue;                                // untouched: stays zero
        v.x = (v.x == 0.0f) ? 0.0f : 1.0f - __expf(v.x);
        v.y = (v.y == 0.0f) ? 0.0f : 1.0f - __expf(v.y);
        v.z = (v.z == 0.0f) ? 0.0f : 1.0f - __expf(v.z);
        v.w = (v.w == 0.0f) ? 0.0f : 1.0f - __expf(v.w);
        out[i] = v;
    }
}

// ---------------------------------------------------------------------------
extern "C" void kernel_launch(void* const* d_in, const int* in_sizes, int n_in,
                              void* d_out, int out_size) {
    const float* coords = (const float*)d_in[0];   // [B, L, 3]
    const int*   chan   = (const int*)  d_in[1];   // [B, L]
    const float* rad    = (const float*)d_in[2];   // [B, L]

    const int BL = in_sizes[1];                    // B * L = 16384
    const int n4  = out_size / 4;
    const int n4c = in_sizes[0] / 4;
    const int B  = out_size / (5 * 32 * 32 * 32);  // 32
    const int L  = BL / B;                         // 512

    // Zero the accumulator via the driver's optimized memset path
    // (graph-capturable memset node; no allocation involved).
    cudaMemsetAsync(d_out, 0, (size_t)out_size * sizeof(float));

    fm_reduce_kernel<<<(n4c + 255) / 256, 256>>>((const float4*)coords, n4c);
    const int sblocks = (BL * 32 + 255) / 256;     // one warp per real atom
    fm_scatter_kernel<<<sblocks, 256>>>(coords, chan, rad, L, BL, (float*)d_out);
    const int fthreads = (n4 + 1) / 2;
    fm_finalize_kernel<<<(fthreads + 255) / 256, 256>>>((float4*)d_out, n4);
}

// round 8
// speedup vs baseline: 1.0115x; 1.0115x over previous
#include <cuda_runtime.h>

// ---------------------------------------------------------------------------
// K1: one WARP per real atom. Crop-local frame: tx = 2*p + 15 (the data-
// dependent box offset F cancels analytically between translation and crop
// start; see derivation in commit message). Crop window is [0, 31].
// Lanes cover the clipped (y,z) footprint with z fastest (coalesced atomics);
// each lane walks x serially using a per-warp exp/exponent table in smem.
__global__ void __launch_bounds__(256)
fm_scatter_kernel(const float* __restrict__ coords,
                  const int*   __restrict__ channel,
                  const float* __restrict__ radius,
                  int L, int BL,
                  float* __restrict__ acc) {
    __shared__ float s_ex[8 * 12];
    __shared__ float s_vx[8 * 12];

    const int wg   = (blockIdx.x * blockDim.x + threadIdx.x) >> 5;
    const int warp = (threadIdx.x >> 5);
    const int lane = threadIdx.x & 31;
    if (wg >= BL) return;
    const int b = wg / L;

    const float* p = coords + (size_t)wg * 3;
    const float px = p[0], py = p[1], pz = p[2];
    const int   ch = channel[wg];
    const float rad = radius[wg] * 1.41421356237309515f;   // RADIUS_SCALE

    const float rt    = rad * 2.0f;                  // radius / res
    const float denom = 0.8649f * rt * rt;           // 0.93^2 * rt^2
    const float inv   = 1.0f / denom;
    const float rcut  = sqrtf(10.0f * denom) + 2e-3f;

    // Crop-local transformed coordinates.
    const float tx = px * 2.0f + 15.0f;
    const float ty = py * 2.0f + 15.0f;
    const float tz = pz * 2.0f + 15.0f;
    const int   dx = (int)floorf(tx);
    const int   dy = (int)floorf(ty);
    const int   dz = (int)floorf(tz);

    // Per-dim clipped local voxel ranges: cube ∩ cutoff-box ∩ crop [0,31].
    const int x0 = max(max(dx - 4, 0),  (int)ceilf (tx - 0.25f - rcut));
    const int x1 = min(min(dx + 6, 31), (int)floorf(tx - 0.25f + rcut));
    const int y0 = max(max(dy - 4, 0),  (int)ceilf (ty - 0.25f - rcut));
    const int y1 = min(min(dy + 6, 31), (int)floorf(ty - 0.25f + rcut));
    const int z0 = max(max(dz - 4, 0),  (int)ceilf (tz - 0.25f - rcut));
    const int z1 = min(min(dz + 6, 31), (int)floorf(tz - 0.25f + rcut));

    const int nx = x1 - x0 + 1, ny = y1 - y0 + 1, nz = z1 - z0 + 1;
    if (nx <= 0 || ny <= 0 || nz <= 0) return;

    // Per-warp x tables (filters above are warp-uniform).
    float* exw = s_ex + warp * 12;
    float* vxw = s_vx + warp * 12;
    if (lane < nx) {
        const float dd = tx - ((float)(x0 + lane) + 0.25f);
        const float ex = dd * dd * inv;
        exw[lane] = ex;
        vxw[lane] = __expf(-ex);
    }
    __syncwarp();

    const int base = (((b * 5 + ch) * 32 + x0) << 10);
    const int total_yz = ny * nz;
    const unsigned magic = 65536u / (unsigned)nz + 1u;   // exact for t*nz < 65536

    for (int t = lane; t < total_yz; t += 32) {
        const int iyr = (int)(((unsigned)t * magic) >> 16);
        const int izr = t - iyr * nz;
        const int gyi = y0 + iyr, gzi = z0 + izr;

        const float ddy = ty - ((float)gyi + 0.25f);
        const float ddz = tz - ((float)gzi + 0.25f);
        const float eyz = (ddy * ddy + ddz * ddz) * inv;
        if (eyz >= 10.0f) continue;                  // whole x-run masked
        const float vyz = __expf(-eyz);

        int idx = base + (gyi << 5) + gzi;
#pragma unroll 4
        for (int xi = 0; xi < nx; ++xi, idx += 1024) {
            const float e = exw[xi] + eyz;
            if (e < 10.0f) {
                const float pv = vxw[xi] * vyz;
                float val;
                if (pv > 0.03125f) {
                    val = __logf(1.0f - pv);
                } else {
                    // ln(1-p) = -p(1 + p(1/2 + p/3)), |err| < 2.5e-7
                    val = -pv * fmaf(pv, fmaf(pv, 0.33333333f, 0.5f), 1.0f);
                }
                atomicAdd(acc + idx, val);
            }
        }
    }
}

// ---------------------------------------------------------------------------
// K2: in-place out = 1 - exp(out); all-zero float4 skip (saves MUFU + write);
// nonzero quads computed branchlessly (exp(0)=1 -> exact 0).
__global__ void fm_finalize_kernel(float4* __restrict__ out, int n4) {
    const int i0 = (blockIdx.x * blockDim.x + threadIdx.x) * 2;
#pragma unroll
    for (int k = 0; k < 2; ++k) {
        const int i = i0 + k;
        if (i >= n4) return;
        float4 v = out[i];
        if ((__float_as_uint(v.x) | __float_as_uint(v.y) |
             __float_as_uint(v.z) | __float_as_uint(v.w)) == 0u)
            continue;                                // untouched: stays zero
        v.x = 1.0f - __expf(v.x);
        v.y = 1.0f - __expf(v.y);
        v.z = 1.0f - __expf(v.z);
        v.w = 1.0f - __expf(v.w);
        out[i] = v;
    }
}

// ---------------------------------------------------------------------------
extern "C" void kernel_launch(void* const* d_in, const int* in_sizes, int n_in,
                              void* d_out, int out_size) {
    const float* coords = (const float*)d_in[0];   // [B, L, 3]
    const int*   chan   = (const int*)  d_in[1];   // [B, L]
    const float* rad    = (const float*)d_in[2];   // [B, L]

    const int BL = in_sizes[1];                    // B * L = 16384
    const int n4 = out_size / 4;
    const int B  = out_size / (5 * 32 * 32 * 32);  // 32
    const int L  = BL / B;                         // 512

    // Zero the accumulator via the driver's memset path (graph memset node).
    cudaMemsetAsync(d_out, 0, (size_t)out_size * sizeof(float));

    const int sblocks = (BL * 32 + 255) / 256;     // one warp per real atom
    fm_scatter_kernel<<<sblocks, 256>>>(coords, chan, rad, L, BL, (float*)d_out);
    const int fthreads = (n4 + 1) / 2;
    fm_finalize_kernel<<<(fthreads + 255) / 256, 256>>>((float4*)d_out, n4);
}

// round 9
// speedup vs baseline: 1.0746x; 1.0624x over previous
#include <cuda_runtime.h>

// ---------------------------------------------------------------------------
// K1: one WARP per real atom. Crop-local frame: t = 2*p + 15 (the data-
// dependent box offset cancels analytically between translation and crop
// start). Crop window is [0, 31]. Lanes cover the clipped (y,z) footprint
// with z fastest (coalesced atomics); each lane walks x serially using a
// per-warp exp table in smem. Mask e<10 is applied as pv > exp(-10).
__global__ void __launch_bounds__(256)
fm_scatter_kernel(const float* __restrict__ coords,
                  const int*   __restrict__ channel,
                  const float* __restrict__ radius,
                  int L, int BL,
                  float* __restrict__ acc) {
    __shared__ float s_vx[8 * 12];

    const int wg   = (blockIdx.x * blockDim.x + threadIdx.x) >> 5;
    const int warp = (threadIdx.x >> 5);
    const int lane = threadIdx.x & 31;
    if (wg >= BL) return;
    const int b = wg / L;

    const float* p = coords + (size_t)wg * 3;
    const float px = p[0], py = p[1], pz = p[2];
    const int   ch = channel[wg];
    const float rad = radius[wg] * 1.41421356237309515f;   // RADIUS_SCALE

    const float rt    = rad * 2.0f;                  // radius / res
    const float denom = 0.8649f * rt * rt;           // 0.93^2 * rt^2
    const float inv   = 1.0f / denom;
    const float rcut  = sqrtf(10.0f * denom) + 2e-3f;

    // Crop-local transformed coordinates.
    const float tx = px * 2.0f + 15.0f;
    const float ty = py * 2.0f + 15.0f;
    const float tz = pz * 2.0f + 15.0f;
    const int   dx = (int)floorf(tx);
    const int   dy = (int)floorf(ty);
    const int   dz = (int)floorf(tz);

    // Per-dim clipped local voxel ranges: cube ∩ cutoff-box ∩ crop [0,31].
    const int x0 = max(max(dx - 4, 0),  (int)ceilf (tx - 0.25f - rcut));
    const int x1 = min(min(dx + 6, 31), (int)floorf(tx - 0.25f + rcut));
    const int y0 = max(max(dy - 4, 0),  (int)ceilf (ty - 0.25f - rcut));
    const int y1 = min(min(dy + 6, 31), (int)floorf(ty - 0.25f + rcut));
    const int z0 = max(max(dz - 4, 0),  (int)ceilf (tz - 0.25f - rcut));
    const int z1 = min(min(dz + 6, 31), (int)floorf(tz - 0.25f + rcut));

    const int nx = x1 - x0 + 1, ny = y1 - y0 + 1, nz = z1 - z0 + 1;
    if (nx <= 0 || ny <= 0 || nz <= 0) return;

    // Per-warp x exp table (filters above are warp-uniform).
    float* vxw = s_vx + warp * 12;
    if (lane < nx) {
        const float dd = tx - ((float)(x0 + lane) + 0.25f);
        vxw[lane] = __expf(-(dd * dd * inv));
    }
    __syncwarp();

    const int base = (((b * 5 + ch) * 32 + x0) << 10);
    const int total_yz = ny * nz;
    const unsigned magic = 65536u / (unsigned)nz + 1u;   // exact for t*nz < 65536

    for (int t = lane; t < total_yz; t += 32) {
        const int iyr = (int)(((unsigned)t * magic) >> 16);
        const int izr = t - iyr * nz;
        const int gyi = y0 + iyr, gzi = z0 + izr;

        const float ddy = ty - ((float)gyi + 0.25f);
        const float ddz = tz - ((float)gzi + 0.25f);
        const float eyz = (ddy * ddy + ddz * ddz) * inv;
        if (eyz >= 10.0f) continue;                  // whole x-run masked
        const float vyz = __expf(-eyz);

        int idx = base + (gyi << 5) + gzi;
#pragma unroll 4
        for (int xi = 0; xi < nx; ++xi, idx += 1024) {
            const float pv = vxw[xi] * vyz;
            if (pv > 4.5399931e-5f) {                // e < 10  <=>  pv > e^-10
                float val;
                if (pv > 0.03125f) {
                    val = __logf(1.0f - pv);
                } else {
                    // ln(1-p) = -p(1 + p(1/2 + p/3)), |err| < 2.5e-7
                    val = -pv * fmaf(pv, fmaf(pv, 0.33333333f, 0.5f), 1.0f);
                }
                atomicAdd(acc + idx, val);
            }
        }
    }
}

// ---------------------------------------------------------------------------
// K2: in-place out = 1 - exp(out); 4 quads per thread loaded up-front (MLP=4);
// all-zero quads skipped (saves MUFU + writeback).
__global__ void fm_finalize_kernel(float4* __restrict__ out, int n4) {
    const int base = blockIdx.x * (blockDim.x * 4) + threadIdx.x;
    float4 v[4];
    int    idx[4];
#pragma unroll
    for (int k = 0; k < 4; ++k) {
        idx[k] = base + k * blockDim.x;
        if (idx[k] < n4) v[k] = out[idx[k]];
        else             v[k] = make_float4(0.f, 0.f, 0.f, 0.f);
    }
#pragma unroll
    for (int k = 0; k < 4; ++k) {
        if (idx[k] >= n4) continue;
        float4 q = v[k];
        if ((__float_as_uint(q.x) | __float_as_uint(q.y) |
             __float_as_uint(q.z) | __float_as_uint(q.w)) == 0u)
            continue;                                // untouched: stays zero
        q.x = 1.0f - __expf(q.x);
        q.y = 1.0f - __expf(q.y);
        q.z = 1.0f - __expf(q.z);
        q.w = 1.0f - __expf(q.w);
        out[idx[k]] = q;
    }
}

// ---------------------------------------------------------------------------
extern "C" void kernel_launch(void* const* d_in, const int* in_sizes, int n_in,
                              void* d_out, int out_size) {
    const float* coords = (const float*)d_in[0];   // [B, L, 3]
    const int*   chan   = (const int*)  d_in[1];   // [B, L]
    const float* rad    = (const float*)d_in[2];   // [B, L]

    const int BL = in_sizes[1];                    // B * L = 16384
    const int n4 = out_size / 4;
    const int B  = out_size / (5 * 32 * 32 * 32);  // 32
    const int L  = BL / B;                         // 512

    // Zero the accumulator via the driver's memset path (graph memset node).
    cudaMemsetAsync(d_out, 0, (size_t)out_size * sizeof(float));

    const int sblocks = (BL * 32 + 255) / 256;     // one warp per real atom
    fm_scatter_kernel<<<sblocks, 256>>>(coords, chan, rad, L, BL, (float*)d_out);
    const int fblocks = (n4 + 256 * 4 - 1) / (256 * 4);
    fm_finalize_kernel<<<fblocks, 256>>>((float4*)d_out, n4);
}